// round 10
// baseline (speedup 1.0000x reference)
#include <cuda_runtime.h>
#include <cuda_bf16.h>
#include <cstdint>

#define Bb 4
#define Nn 4096
#define Dd 256
#define Mm (Bb*Nn)

__device__ __nv_bfloat16 g_xhi[Mm*Dd], g_xlo[Mm*Dd];
__device__ __nv_bfloat16 g_Whi[3*Dd*Dd], g_Wlo[3*Dd*Dd];
__device__ __nv_bfloat16 g_Qhi[Mm*Dd], g_Qlo[Mm*Dd];
__device__ __nv_bfloat16 g_Khi[Mm*Dd], g_Klo[Mm*Dd];
__device__ __nv_bfloat16 g_Vhi[Mm*Dd], g_Vlo[Mm*Dd];

// ---------------- mma.sync / ldmatrix / cp.async ----------------
__device__ __forceinline__ uint32_t smem_u32(const void* p)
{ uint32_t a;
  asm("{ .reg .u64 t; cvta.to.shared.u64 t, %1; cvt.u32.u64 %0, t; }":"=r"(a):"l"(p));
  return a; }

__device__ __forceinline__ void ldsm4(uint32_t* r, uint32_t a)
{ asm volatile("ldmatrix.sync.aligned.m8n8.x4.shared.b16 {%0,%1,%2,%3}, [%4];"
    : "=r"(r[0]), "=r"(r[1]), "=r"(r[2]), "=r"(r[3]) : "r"(a)); }
__device__ __forceinline__ void ldsm4t(uint32_t* r, uint32_t a)
{ asm volatile("ldmatrix.sync.aligned.m8n8.x4.trans.shared.b16 {%0,%1,%2,%3}, [%4];"
    : "=r"(r[0]), "=r"(r[1]), "=r"(r[2]), "=r"(r[3]) : "r"(a)); }

__device__ __forceinline__ void mma16816(float* c, const uint32_t* a, const uint32_t* b)
{ asm volatile("mma.sync.aligned.m16n8k16.row.col.f32.bf16.bf16.f32 "
    "{%0,%1,%2,%3}, {%4,%5,%6,%7}, {%8,%9}, {%0,%1,%2,%3};"
    : "+f"(c[0]), "+f"(c[1]), "+f"(c[2]), "+f"(c[3])
    : "r"(a[0]), "r"(a[1]), "r"(a[2]), "r"(a[3]), "r"(b[0]), "r"(b[1])); }

#define CPA16(d, s) asm volatile("cp.async.cg.shared.global [%0], [%1], 16;"::"r"(d),"l"(s))
#define CPCOMMIT()  asm volatile("cp.async.commit_group;":::"memory")
#define CPWAIT0()   asm volatile("cp.async.wait_group 0;":::"memory")

// swizzled blocked-atom layouts (Swizzle<3,4,3>, 128B rows)
#define SWZ(o) ((o) ^ (((o) >> 3) & 0x70))
__device__ __forceinline__ uint32_t xswz(int r, int cb)   // 128 rows x 512B
{ return SWZ((uint32_t)((((r>>3) + (cb>>7)*16)*1024) + (r&7)*128 + (cb&127))); }
__device__ __forceinline__ uint32_t qswz(int r, int cb)   // 64 rows x 512B
{ return SWZ((uint32_t)((((r>>3) + (cb>>7)*8)*1024) + (r&7)*128 + (cb&127))); }
__device__ __forceinline__ uint32_t kswz(int r, int cb)   // 32 rows x 512B
{ return SWZ((uint32_t)((((r>>3) + (cb>>7)*4)*1024) + (r&7)*128 + (cb&127))); }
__device__ __forceinline__ uint32_t pswz(int r, int cb)   // 128B rows
{ return SWZ((uint32_t)(r*128 + cb)); }

// attention SMEM map
#define SM_QH 0
#define SM_QL 32768
#define SM_K  65536    // 2 stages x 32KB (Kh 16K | Kl 16K)
#define SM_V  131072   // 2 stages x 32KB (Vh 16K | Vl 16K)
#define SM_P  196608   // 2 x 8KB
#define SM_TOT 212992

// qkvmm SMEM map
#define SMX_H 0
#define SMX_L 65536
#define SMW_H 131072
#define SMW_L 163840
#define SM_QKV_TOT 196608

// ---------------------------------------------------------------------------
// convX: split x fp32 -> bf16 hi/lo
// ---------------------------------------------------------------------------
__global__ __launch_bounds__(256, 4) void convX_kernel(const float* __restrict__ x)
{
    size_t i = (size_t)(blockIdx.x * 256 + threadIdx.x) * 4;
    float4 v = *(const float4*)&x[i];
    float a[4] = {v.x, v.y, v.z, v.w};
    ushort h[4], l[4];
    #pragma unroll
    for (int k = 0; k < 4; k++) {
        __nv_bfloat16 hb = __float2bfloat16(a[k]);
        h[k] = __bfloat16_as_ushort(hb);
        l[k] = __bfloat16_as_ushort(__float2bfloat16(a[k] - __bfloat162float(hb)));
    }
    *(uint2*)&g_xhi[i] = make_uint2(h[0] | ((uint32_t)h[1]<<16), h[2] | ((uint32_t)h[3]<<16));
    *(uint2*)&g_xlo[i] = make_uint2(l[0] | ((uint32_t)l[1]<<16), l[2] | ((uint32_t)l[3]<<16));
}

// convW: split weight matrices fp32 -> bf16 hi/lo
__global__ __launch_bounds__(256, 4)
void convW_kernel(const float* __restrict__ Wq, const float* __restrict__ Wk,
                  const float* __restrict__ Wv)
{
    const int z = blockIdx.y;
    const float* in = (z == 0) ? Wq : (z == 1) ? Wk : Wv;
    size_t base = (size_t)z * Dd * Dd;
    size_t i = (size_t)(blockIdx.x * 256 + threadIdx.x) * 4;
    float4 v = *(const float4*)&in[i];
    float a[4] = {v.x, v.y, v.z, v.w};
    ushort h[4], l[4];
    #pragma unroll
    for (int k = 0; k < 4; k++) {
        __nv_bfloat16 hb = __float2bfloat16(a[k]);
        h[k] = __bfloat16_as_ushort(hb);
        l[k] = __bfloat16_as_ushort(__float2bfloat16(a[k] - __bfloat162float(hb)));
    }
    *(uint2*)&g_Whi[base + i] = make_uint2(h[0] | ((uint32_t)h[1]<<16), h[2] | ((uint32_t)h[3]<<16));
    *(uint2*)&g_Wlo[base + i] = make_uint2(l[0] | ((uint32_t)l[1]<<16), l[2] | ((uint32_t)l[3]<<16));
}

// ---------------------------------------------------------------------------
// qkvmm: HMMA QKV projection (unchanged from R9 — known good)
// ---------------------------------------------------------------------------
__global__ __launch_bounds__(256, 1)
void qkvmm_kernel(const float* __restrict__ bq, const float* __restrict__ bk,
                  const float* __restrict__ bv)
{
    extern __shared__ char sm[];
    uint32_t sb = smem_u32(sm);
    const int t = threadIdx.x, lane = t & 31, wid = t >> 5;
    const int z = blockIdx.x;
    const int m0 = blockIdx.y * 128;
    const float* bias = (z == 0) ? bq : (z == 1) ? bk : bv;
    __nv_bfloat16* ohi = (z == 0) ? g_Qhi : (z == 1) ? g_Khi : g_Vhi;
    __nv_bfloat16* olo = (z == 0) ? g_Qlo : (z == 1) ? g_Klo : g_Vlo;
    const char* xh = (const char*)g_xhi + (size_t)m0 * 512;
    const char* xl = (const char*)g_xlo + (size_t)m0 * 512;
    const char* wh = (const char*)g_Whi + (size_t)z * 131072;
    const char* wl = (const char*)g_Wlo + (size_t)z * 131072;

    #pragma unroll
    for (int i = 0; i < 16; i++) {
        int id = i*256 + t;
        int row = id >> 5, cb = (id & 31) * 16;
        uint32_t o = xswz(row, cb);
        *(uint4*)(sm + SMX_H + o) = *(const uint4*)(xh + (size_t)row*512 + cb);
        *(uint4*)(sm + SMX_L + o) = *(const uint4*)(xl + (size_t)row*512 + cb);
    }

    const int lrow = lane & 15, lk16 = (lane >> 4) * 16;
    const int wrow = (lane >> 4) * 8 + (lane & 7);
    const int kb16 = ((lane >> 3) & 1) * 16;
    const int g = lane >> 2, tq = lane & 3;

    for (int et = 0; et < 4; et++) {
        __syncthreads();
        const char* wph = wh + (size_t)et * 64 * 512;
        const char* wpl = wl + (size_t)et * 64 * 512;
        #pragma unroll
        for (int i = 0; i < 8; i++) {
            int id = i*256 + t;
            int row = id >> 5, cb = (id & 31) * 16;
            uint32_t o = qswz(row, cb);
            *(uint4*)(sm + SMW_H + o) = *(const uint4*)(wph + (size_t)row*512 + cb);
            *(uint4*)(sm + SMW_L + o) = *(const uint4*)(wpl + (size_t)row*512 + cb);
        }
        __syncthreads();

        float acc[8][4] = {};
        #pragma unroll
        for (int ks = 0; ks < 16; ks++) {
            uint32_t axh[4], axl[4];
            uint32_t xo = xswz(16*wid + lrow, ks*32 + lk16);
            ldsm4(axh, sb + SMX_H + xo);
            ldsm4(axl, sb + SMX_L + xo);
            #pragma unroll
            for (int n16 = 0; n16 < 4; n16++) {
                uint32_t bwh[4], bwl[4];
                uint32_t wo = qswz(n16*16 + wrow, ks*32 + kb16);
                ldsm4(bwh, sb + SMW_H + wo);
                ldsm4(bwl, sb + SMW_L + wo);
                mma16816(acc[n16*2],   axh, bwh);
                mma16816(acc[n16*2],   axh, bwl);
                mma16816(acc[n16*2],   axl, bwh);
                mma16816(acc[n16*2+1], axh, bwh + 2);
                mma16816(acc[n16*2+1], axh, bwl + 2);
                mma16816(acc[n16*2+1], axl, bwh + 2);
            }
        }

        size_t row0 = (size_t)(m0 + 16*wid + g);
        #pragma unroll
        for (int n2 = 0; n2 < 8; n2++) {
            int col = et*64 + n2*8 + 2*tq;
            float b0 = bias[col], b1 = bias[col + 1];
            float v00 = acc[n2][0] + b0, v01 = acc[n2][1] + b1;
            float v10 = acc[n2][2] + b0, v11 = acc[n2][3] + b1;
            __nv_bfloat16 h00 = __float2bfloat16(v00), h01 = __float2bfloat16(v01);
            __nv_bfloat16 h10 = __float2bfloat16(v10), h11 = __float2bfloat16(v11);
            uint32_t hw0 = __bfloat16_as_ushort(h00) | ((uint32_t)__bfloat16_as_ushort(h01) << 16);
            uint32_t hw1 = __bfloat16_as_ushort(h10) | ((uint32_t)__bfloat16_as_ushort(h11) << 16);
            ushort l00 = __bfloat16_as_ushort(__float2bfloat16(v00 - __bfloat162float(h00)));
            ushort l01 = __bfloat16_as_ushort(__float2bfloat16(v01 - __bfloat162float(h01)));
            ushort l10 = __bfloat16_as_ushort(__float2bfloat16(v10 - __bfloat162float(h10)));
            ushort l11 = __bfloat16_as_ushort(__float2bfloat16(v11 - __bfloat162float(h11)));
            uint32_t lw0 = l00 | ((uint32_t)l01 << 16);
            uint32_t lw1 = l10 | ((uint32_t)l11 << 16);
            *(uint32_t*)&ohi[row0*Dd + col]       = hw0;
            *(uint32_t*)&olo[row0*Dd + col]       = lw0;
            *(uint32_t*)&ohi[(row0 + 8)*Dd + col] = hw1;
            *(uint32_t*)&olo[(row0 + 8)*Dd + col] = lw1;
        }
    }
}

// ---------------------------------------------------------------------------
// Warp-specialized HMMA flash attention: warps 0-3 = S+softmax, warps 4-7 = PV.
// Br=64, Bc=32; K/V 2-stage cp.async rings; P double-buffered; 1 sync/tile.
// ---------------------------------------------------------------------------
__global__ __launch_bounds__(256, 1)
void attn_kernel(const int* __restrict__ mask, float* __restrict__ out)
{
    extern __shared__ char sm[];
    uint32_t sb = smem_u32(sm);
    const int t = threadIdx.x, lane = t & 31, wid = t >> 5;
    const int b = blockIdx.y, q0 = blockIdx.x * 64;
    const int g = lane >> 2, tq = lane & 3;
    const int lrow = lane & 15, lk16 = (lane >> 4) * 16;

    // Q hi/lo -> smem (blocked swizzled)
    {
        const char* qh = (const char*)&g_Qhi[(size_t)(b*Nn + q0)*Dd];
        const char* ql = (const char*)&g_Qlo[(size_t)(b*Nn + q0)*Dd];
        #pragma unroll
        for (int i = 0; i < 8; i++) {
            int id = i*256 + t;
            int row = id >> 5, cb = (id & 31) * 16;
            uint32_t o = qswz(row, cb);
            *(uint4*)(sm + SM_QH + o) = *(const uint4*)(qh + (size_t)row*512 + cb);
            *(uint4*)(sm + SM_QL + o) = *(const uint4*)(ql + (size_t)row*512 + cb);
        }
    }

    const char* baseKh = (const char*)&g_Khi[(size_t)(b*Nn)*Dd];
    const char* baseKl = (const char*)&g_Klo[(size_t)(b*Nn)*Dd];
    const char* baseVh = (const char*)&g_Vhi[(size_t)(b*Nn)*Dd];
    const char* baseVl = (const char*)&g_Vlo[(size_t)(b*Nn)*Dd];

    // prologue: K(0) into K stage 0
    #pragma unroll
    for (int i = 0; i < 4; i++) {
        int id = i*256 + t;
        int row = id >> 5, cb = (id & 31) * 16;
        uint32_t o = kswz(row, cb);
        CPA16(sb + SM_K + o,         baseKh + (size_t)row*512 + cb);
        CPA16(sb + SM_K + 16384 + o, baseKl + (size_t)row*512 + cb);
    }
    CPCOMMIT();

    float l0 = 0.f, l1 = 0.f;        // S-warps: row sums
    float oo[32][4];                  // PV-warps: O accum (16 rows x 256 cols)
    #pragma unroll
    for (int i = 0; i < 32; i++)
        { oo[i][0] = 0.f; oo[i][1] = 0.f; oo[i][2] = 0.f; oo[i][3] = 0.f; }

    const int key0 = (lane >> 4)*8 + (lane & 7);
    const int kb16 = ((lane >> 3) & 1) * 16;
    const int vr   = (lane & 7) + ((lane >> 3) & 1) * 8;

    for (int j = 0; j <= 128; j++) {
        CPWAIT0();
        __syncthreads();   // K(j), V(j-1), P(j-1) all visible

        // issue next-tile loads (all warps)
        if (j <= 126) {
            uint32_t dst = sb + SM_K + ((j+1)&1)*32768;
            size_t gb = (size_t)(j+1)*16384;
            #pragma unroll
            for (int i = 0; i < 4; i++) {
                int id = i*256 + t;
                int row = id >> 5, cb = (id & 31) * 16;
                uint32_t o = kswz(row, cb);
                CPA16(dst + o,         baseKh + gb + (size_t)row*512 + cb);
                CPA16(dst + 16384 + o, baseKl + gb + (size_t)row*512 + cb);
            }
        }
        if (j <= 127) {
            uint32_t dst = sb + SM_V + (j&1)*32768;
            size_t gb = (size_t)j*16384;
            #pragma unroll
            for (int i = 0; i < 4; i++) {
                int id = i*256 + t;
                int row = id >> 5, cb = (id & 31) * 16;
                uint32_t o = kswz(row, cb);
                CPA16(dst + o,         baseVh + gb + (size_t)row*512 + cb);
                CPA16(dst + 16384 + o, baseVl + gb + (size_t)row*512 + cb);
            }
        }
        CPCOMMIT();

        if (wid < 4) {
            // ---------------- S-group ----------------
            if (j < 128) {
                uint32_t sKh = sb + SM_K + (j&1)*32768;
                uint32_t sKl = sKh + 16384;
                const int* mrow = mask + (size_t)(b*Nn + q0 + 16*wid + g)*Nn + j*32 + 2*tq;
                int2 mk0[4], mk1[4];
                #pragma unroll
                for (int nn = 0; nn < 4; nn++) {
                    mk0[nn] = *(const int2*)(mrow + nn*8);
                    mk1[nn] = *(const int2*)(mrow + 8*(size_t)Nn + nn*8);
                }
                float shh[4][4] = {}, shl[4][4] = {}, slh[4][4] = {};
                #pragma unroll
                for (int ks = 0; ks < 16; ks++) {
                    uint32_t aqh[4], aql[4], bk0[4], bk1[4], bl0[4], bl1[4];
                    uint32_t qo = qswz(16*wid + lrow, ks*32 + lk16);
                    ldsm4(aqh, sb + SM_QH + qo);
                    ldsm4(aql, sb + SM_QL + qo);
                    uint32_t ko0 = kswz(key0,      ks*32 + kb16);
                    uint32_t ko1 = kswz(16 + key0, ks*32 + kb16);
                    ldsm4(bk0, sKh + ko0); ldsm4(bk1, sKh + ko1);
                    ldsm4(bl0, sKl + ko0); ldsm4(bl1, sKl + ko1);
                    mma16816(shh[0], aqh, bk0); mma16816(shh[1], aqh, bk0 + 2);
                    mma16816(shh[2], aqh, bk1); mma16816(shh[3], aqh, bk1 + 2);
                    mma16816(shl[0], aqh, bl0); mma16816(shl[1], aqh, bl0 + 2);
                    mma16816(shl[2], aqh, bl1); mma16816(shl[3], aqh, bl1 + 2);
                    mma16816(slh[0], aql, bk0); mma16816(slh[1], aql, bk0 + 2);
                    mma16816(slh[2], aql, bk1); mma16816(slh[3], aql, bk1 + 2);
                }
                const float sc = 0.0625f;
                char* pb = sm + SM_P + (j&1)*8192;
                int row0 = 16*wid + g;
                #pragma unroll
                for (int nn = 0; nn < 4; nn++) {
                    float sA0 = shh[nn][0] + shl[nn][0] + slh[nn][0];
                    float sA1 = shh[nn][1] + shl[nn][1] + slh[nn][1];
                    float sB0 = shh[nn][2] + shl[nn][2] + slh[nn][2];
                    float sB1 = shh[nn][3] + shl[nn][3] + slh[nn][3];
                    float p0 = mk0[nn].x ? __expf(sA0*sc) : 0.f;
                    float p1 = mk0[nn].y ? __expf(sA1*sc) : 0.f;
                    float p2 = mk1[nn].x ? __expf(sB0*sc) : 0.f;
                    float p3 = mk1[nn].y ? __expf(sB1*sc) : 0.f;
                    l0 += p0 + p1;
                    l1 += p2 + p3;
                    uint32_t w0 = __bfloat16_as_ushort(__float2bfloat16(p0))
                                | ((uint32_t)__bfloat16_as_ushort(__float2bfloat16(p1)) << 16);
                    uint32_t w1 = __bfloat16_as_ushort(__float2bfloat16(p2))
                                | ((uint32_t)__bfloat16_as_ushort(__float2bfloat16(p3)) << 16);
                    int cb = nn*16 + 4*tq;
                    *(uint32_t*)(pb + pswz(row0,     cb)) = w0;
                    *(uint32_t*)(pb + pswz(row0 + 8, cb)) = w1;
                }
            } else {
                // final iter: publish row sums
                float a0 = l0, a1 = l1;
                a0 += __shfl_xor_sync(0xffffffffu, a0, 1);
                a0 += __shfl_xor_sync(0xffffffffu, a0, 2);
                a1 += __shfl_xor_sync(0xffffffffu, a1, 1);
                a1 += __shfl_xor_sync(0xffffffffu, a1, 2);
                float* Ls = (float*)(sm + SM_K);   // K ring dead
                if (tq == 0) {
                    Ls[16*wid + g]     = a0;
                    Ls[16*wid + 8 + g] = a1;
                }
            }
        } else {
            // ---------------- PV-group ----------------
            if (j >= 1) {
                const int i_ = j - 1;
                const int pw = wid - 4;
                uint32_t sVh = sb + SM_V + (i_&1)*32768;
                uint32_t sVl = sVh + 16384;
                uint32_t pbuf = sb + SM_P + (i_&1)*8192;
                #pragma unroll
                for (int kc = 0; kc < 2; kc++) {
                    uint32_t aph[4];
                    ldsm4(aph, pbuf + pswz(16*pw + lrow, kc*32 + lk16));
                    #pragma unroll
                    for (int c16 = 0; c16 < 16; c16++) {
                        int vcb = (c16*16 + (lane >> 4)*8) * 2;
                        uint32_t vo = kswz(kc*16 + vr, vcb);
                        uint32_t bvh[4], bvl[4];
                        ldsm4t(bvh, sVh + vo);
                        ldsm4t(bvl, sVl + vo);
                        mma16816(oo[c16*2],     aph, bvh);
                        mma16816(oo[c16*2],     aph, bvl);
                        mma16816(oo[c16*2 + 1], aph, bvh + 2);
                        mma16816(oo[c16*2 + 1], aph, bvl + 2);
                    }
                }
            }
        }
    }

    __syncthreads();   // Ls written, all PV done
    if (wid >= 4) {
        const int pw = wid - 4;
        const float* Ls = (const float*)(sm + SM_K);
        float inv0 = 1.0f / Ls[16*pw + g];
        float inv1 = 1.0f / Ls[16*pw + 8 + g];
        size_t row0 = (size_t)(b*Nn + q0 + 16*pw + g);
        #pragma unroll
        for (int n8 = 0; n8 < 32; n8++) {
            int col = n8*8 + 2*tq;
            *(float2*)&out[row0*Dd + col]     = make_float2(oo[n8][0]*inv0, oo[n8][1]*inv0);
            *(float2*)&out[(row0+8)*Dd + col] = make_float2(oo[n8][2]*inv1, oo[n8][3]*inv1);
        }
    }
}

extern "C" void kernel_launch(void* const* d_in, const int* in_sizes, int n_in,
                              void* d_out, int out_size)
{
    const float* x    = (const float*)d_in[0];
    const int*   mask = (const int*)  d_in[1];
    const float* Wq   = (const float*)d_in[2];
    const float* bq   = (const float*)d_in[3];
    const float* Wk   = (const float*)d_in[4];
    const float* bk   = (const float*)d_in[5];
    const float* Wv   = (const float*)d_in[6];
    const float* bv   = (const float*)d_in[7];
    float* out = (float*)d_out;

    cudaFuncSetAttribute(attn_kernel,
                         cudaFuncAttributeMaxDynamicSharedMemorySize, SM_TOT);
    cudaFuncSetAttribute(qkvmm_kernel,
                         cudaFuncAttributeMaxDynamicSharedMemorySize, SM_QKV_TOT);

    convX_kernel<<<Mm*Dd/1024, 256>>>(x);
    dim3 gW(Dd*Dd/1024, 3);
    convW_kernel<<<gW, 256>>>(Wq, Wk, Wv);
    dim3 gM(3, Mm/128);
    qkvmm_kernel<<<gM, 256, SM_QKV_TOT>>>(bq, bk, bv);
    dim3 g2(Nn/64, Bb);
    attn_kernel<<<g2, 256, SM_TOT>>>(mask, out);
}